// round 5
// baseline (speedup 1.0000x reference)
#include <cuda_runtime.h>
#include <cuda_fp16.h>
#include <math.h>
#include <stdint.h>

#define BATCH 64
#define SEQ 512
#define INPUT_DIM 512
#define HIDDEN 128
#define G3 384            // 3*HIDDEN
#define NUM_LAYERS 5
#define OUTPUT_DIM 96

typedef unsigned long long ull;

// ---------------- scratch (no allocs allowed) ----------------
__device__ float g_gx[BATCH * SEQ * G3];        // per-layer input gates
__device__ float g_ya[BATCH * SEQ * HIDDEN];    // ping
__device__ float g_yb[BATCH * SEQ * HIDDEN];    // pong

// ---------------- packed f32x2 helpers ----------------
__device__ __forceinline__ ull pk2(float a, float b) {
    ull r; asm("mov.b64 %0, {%1, %2};" : "=l"(r) : "f"(a), "f"(b)); return r;
}
__device__ __forceinline__ void upk2(ull v, float& a, float& b) {
    asm("mov.b64 {%0, %1}, %2;" : "=f"(a), "=f"(b) : "l"(v));
}
__device__ __forceinline__ ull ffma2(ull a, ull b, ull c) {
    ull d; asm("fma.rn.f32x2 %0, %1, %2, %3;" : "=l"(d) : "l"(a), "l"(b), "l"(c)); return d;
}
__device__ __forceinline__ float sigm_fast(float x) {
    float e = __expf(-x);
    return __fdividef(1.0f, 1.0f + e);
}
__device__ __forceinline__ float tanh_fast(float x) {
    float e = __expf(-2.0f * x);
    return 1.0f - __fdividef(2.0f * e, 1.0f + e);
}
__device__ __forceinline__ uint32_t packh2(float a, float b) {
    __half2 h = __floats2half2_rn(a, b);
    return *(uint32_t*)&h;
}

// mma.sync m16n8k16 row.col f32.f16.f16.f32 (legacy HMMA — baseline PTX, sm_80+)
__device__ __forceinline__ void mma16816(float d[4], const uint32_t a[4],
                                         uint32_t b0, uint32_t b1,
                                         const float c[4]) {
    asm volatile(
        "mma.sync.aligned.m16n8k16.row.col.f32.f16.f16.f32 "
        "{%0,%1,%2,%3}, {%4,%5,%6,%7}, {%8,%9}, {%10,%11,%12,%13};\n"
        : "=f"(d[0]), "=f"(d[1]), "=f"(d[2]), "=f"(d[3])
        : "r"(a[0]), "r"(a[1]), "r"(a[2]), "r"(a[3]),
          "r"(b0), "r"(b1),
          "f"(c[0]), "f"(c[1]), "f"(c[2]), "f"(c[3]));
}

// ---------------- GEMM: C[M x 384] = A[M x K] * W[384 x K]^T + bias ----------------
__global__ __launch_bounds__(256) void gemm_nt_kernel(
    const float* __restrict__ A, const float* __restrict__ W,
    const float* __restrict__ bias, float* __restrict__ C,
    int M, int K)
{
    __shared__ __align__(16) float Ast[16][64];
    __shared__ __align__(16) float Bst[16][64];

    const int tid = threadIdx.x;
    const int m0 = blockIdx.y * 64;
    const int n0 = blockIdx.x * 64;
    const int lrow = tid >> 2;
    const int lkc  = (tid & 3) << 2;
    const float* Ap = A + (size_t)(m0 + lrow) * K + lkc;
    const float* Wp = W + (size_t)(n0 + lrow) * K + lkc;
    const int tx = tid & 15;
    const int ty = tid >> 4;

    ull acc[4][2];
#pragma unroll
    for (int i = 0; i < 4; i++) { acc[i][0] = pk2(0.f, 0.f); acc[i][1] = pk2(0.f, 0.f); }

    float4 av = *(const float4*)(Ap);
    float4 bv = *(const float4*)(Wp);

    for (int kt = 0; kt < K; kt += 16) {
        __syncthreads();
        Ast[lkc + 0][lrow] = av.x; Ast[lkc + 1][lrow] = av.y;
        Ast[lkc + 2][lrow] = av.z; Ast[lkc + 3][lrow] = av.w;
        Bst[lkc + 0][lrow] = bv.x; Bst[lkc + 1][lrow] = bv.y;
        Bst[lkc + 2][lrow] = bv.z; Bst[lkc + 3][lrow] = bv.w;
        __syncthreads();
        if (kt + 16 < K) {
            av = *(const float4*)(Ap + kt + 16);
            bv = *(const float4*)(Wp + kt + 16);
        }
#pragma unroll
        for (int k = 0; k < 16; k++) {
            float4 a4 = *(const float4*)&Ast[k][ty << 2];
            ulonglong2 b2 = *(const ulonglong2*)&Bst[k][tx << 2];
            ull pa;
            pa = pk2(a4.x, a4.x);
            acc[0][0] = ffma2(pa, b2.x, acc[0][0]); acc[0][1] = ffma2(pa, b2.y, acc[0][1]);
            pa = pk2(a4.y, a4.y);
            acc[1][0] = ffma2(pa, b2.x, acc[1][0]); acc[1][1] = ffma2(pa, b2.y, acc[1][1]);
            pa = pk2(a4.z, a4.z);
            acc[2][0] = ffma2(pa, b2.x, acc[2][0]); acc[2][1] = ffma2(pa, b2.y, acc[2][1]);
            pa = pk2(a4.w, a4.w);
            acc[3][0] = ffma2(pa, b2.x, acc[3][0]); acc[3][1] = ffma2(pa, b2.y, acc[3][1]);
        }
    }
#pragma unroll
    for (int i = 0; i < 4; i++) {
        int m = m0 + (ty << 2) + i;
        float c0, c1, c2, c3;
        upk2(acc[i][0], c0, c1);
        upk2(acc[i][1], c2, c3);
        int n = n0 + (tx << 2);
        float* Cp = C + (size_t)m * G3 + n;
        Cp[0] = c0 + bias[n + 0];
        Cp[1] = c1 + bias[n + 1];
        Cp[2] = c2 + bias[n + 2];
        Cp[3] = c3 + bias[n + 3];
    }
}

// ---------------- GRU recurrence via mma.sync ----------------
// One CTA per batch, 384 threads = 12 warps. Warp w owns gate-rows
// [32w, 32w+32) as two m16 tiles; W_hh rows live in fp16 A-fragments in
// registers. B cols: col0 = fp16_hi(h), col1 = fp16_lo(h) -> one MMA gives
// the exact-ish fp32 dot as D[:,0]+D[:,1] (c0+c1 / c2+c3 of lane%4==0).
__global__ __launch_bounds__(384, 1) void gru_rec_mma(
    const float* __restrict__ w_hh,   // [384][128]
    const float* __restrict__ b_hh,   // [384]
    float* __restrict__ y)            // [BATCH][SEQ][HIDDEN]
{
    __shared__ float gh_s[G3];
    __shared__ uint32_t h2hi[64];   // half2: h_hi pairs
    __shared__ uint32_t h2lo[64];   // half2: h_lo pairs

    const int b = blockIdx.x;
    const int tid = threadIdx.x;
    const int wid = tid >> 5;
    const int lane = tid & 31;
    const int g  = lane >> 2;       // 0..7
    const int tg = lane & 3;        // 0..3
    const int j = tid;              // gate index for tid<128
    const bool gate_thr = (tid < HIDDEN);

    // ---- preload W_hh into A fragments (fp32 -> fp16) ----
    uint32_t afr[2][8][4];
#pragma unroll
    for (int i = 0; i < 2; i++) {
        const int mbase = wid * 32 + i * 16;
        const float* r0p = w_hh + (size_t)(mbase + g) * HIDDEN;
        const float* r1p = w_hh + (size_t)(mbase + 8 + g) * HIDDEN;
#pragma unroll
        for (int kt = 0; kt < 8; kt++) {
            const int c0 = kt * 16 + 2 * tg;
            float2 v00 = *(const float2*)(r0p + c0);
            float2 v10 = *(const float2*)(r1p + c0);
            float2 v01 = *(const float2*)(r0p + c0 + 8);
            float2 v11 = *(const float2*)(r1p + c0 + 8);
            afr[i][kt][0] = packh2(v00.x, v00.y);
            afr[i][kt][1] = packh2(v10.x, v10.y);
            afr[i][kt][2] = packh2(v01.x, v01.y);
            afr[i][kt][3] = packh2(v11.x, v11.y);
        }
    }

    // gate-thread biases
    float br = 0.f, bz = 0.f, bn = 0.f;
    if (gate_thr) {
        br = b_hh[j];
        bz = b_hh[j + HIDDEN];
        bn = b_hh[j + 2 * HIDDEN];
    }

    // zero h (hi/lo)
    if (tid < 64) { h2hi[tid] = 0u; h2lo[tid] = 0u; }

    const float* gxb = g_gx + (size_t)b * SEQ * G3;
    float* yb = y + (size_t)b * SEQ * HIDDEN;

    // prefetch t=0 gx
    float xr = 0.f, xz = 0.f, xn = 0.f;
    if (gate_thr) {
        xr = gxb[j];
        xz = gxb[j + HIDDEN];
        xn = gxb[j + 2 * HIDDEN];
    }
    float hreg = 0.0f;
    __syncthreads();

    for (int t = 0; t < SEQ; t++) {
        // prefetch next gx (gate threads only)
        float nxr = 0.f, nxz = 0.f, nxn = 0.f;
        if (gate_thr && t + 1 < SEQ) {
            const float* g1 = gxb + (t + 1) * G3;
            nxr = __ldg(g1 + j);
            nxz = __ldg(g1 + j + HIDDEN);
            nxn = __ldg(g1 + j + 2 * HIDDEN);
        }

        // ---- build B fragments (same for all warps) ----
        uint32_t b0[8], b1[8];
#pragma unroll
        for (int kt = 0; kt < 8; kt++) { b0[kt] = 0u; b1[kt] = 0u; }
        if (lane < 8) {
            const uint32_t* src = (lane < 4) ? h2hi : h2lo;
#pragma unroll
            for (int kt = 0; kt < 8; kt++) {
                b0[kt] = src[kt * 8 + tg];
                b1[kt] = src[kt * 8 + 4 + tg];
            }
        }

        // ---- MMA: 2 m-tiles x 8 k-tiles, 2 accumulator chains each ----
#pragma unroll
        for (int i = 0; i < 2; i++) {
            float da[4] = {0.f, 0.f, 0.f, 0.f};
            float db[4] = {0.f, 0.f, 0.f, 0.f};
#pragma unroll
            for (int kt = 0; kt < 8; kt += 2) {
                mma16816(da, afr[i][kt],     b0[kt],     b1[kt],     da);
                mma16816(db, afr[i][kt + 1], b0[kt + 1], b1[kt + 1], db);
            }
            if (tg == 0) {
                const int mbase = wid * 32 + i * 16;
                gh_s[mbase + g]     = (da[0] + db[0]) + (da[1] + db[1]); // col0+col1
                gh_s[mbase + 8 + g] = (da[2] + db[2]) + (da[3] + db[3]);
            }
        }
        __syncthreads();

        // ---- gates (threads 0..127) ----
        if (gate_thr) {
            float r = sigm_fast(xr + gh_s[j] + br);
            float z = sigm_fast(xz + gh_s[j + HIDDEN] + bz);
            float n = tanh_fast(xn + r * (gh_s[j + 2 * HIDDEN] + bn));
            float hn = (1.0f - z) * n + z * hreg;
            hreg = hn;

            // split into hi/lo fp16 and pack pairs via shfl
            float hnN = __shfl_down_sync(0xffffffffu, hn, 1);
            if ((j & 1) == 0) {
                __half hiS = __float2half_rn(hn);
                __half hiN = __float2half_rn(hnN);
                float loS = hn - __half2float(hiS);
                float loN = hnN - __half2float(hiN);
                __half2 hh; hh.x = hiS; hh.y = hiN;
                h2hi[j >> 1] = *(uint32_t*)&hh;
                h2lo[j >> 1] = packh2(loS, loN);
            }
            yb[t * HIDDEN + j] = hn;
        }
        __syncthreads();

        xr = nxr; xz = nxz; xn = nxn;
    }
}

// ---------------- final FC on last timestep ----------------
__global__ void fc_kernel(const float* __restrict__ yfinal,
                          const float* __restrict__ fc_w,
                          const float* __restrict__ fc_b,
                          float* __restrict__ out)
{
    const int b = blockIdx.x;
    const int o = threadIdx.x;   // 0..95
    const float* h = yfinal + ((size_t)b * SEQ + (SEQ - 1)) * HIDDEN;
    const float* w = fc_w + (size_t)o * HIDDEN;
    float acc = fc_b[o];
#pragma unroll 16
    for (int k = 0; k < HIDDEN; k++) acc = fmaf(h[k], w[k], acc);
    out[b * OUTPUT_DIM + o] = acc;
}

// ---------------- host launch ----------------
extern "C" void kernel_launch(void* const* d_in, const int* in_sizes, int n_in,
                              void* d_out, int out_size)
{
    const float* x        = (const float*)d_in[0];  // [64,512,512]
    const float* w_ih0    = (const float*)d_in[1];  // [384,512]
    const float* w_ihrest = (const float*)d_in[2];  // [4,384,128]
    const float* w_hh     = (const float*)d_in[3];  // [5,384,128]
    const float* b_ih     = (const float*)d_in[4];  // [5,384]
    const float* b_hh     = (const float*)d_in[5];  // [5,384]
    const float* fc_w     = (const float*)d_in[6];  // [96,128]
    const float* fc_b     = (const float*)d_in[7];  // [96]
    float* out = (float*)d_out;

    float *gx, *ya, *yb;
    cudaGetSymbolAddress((void**)&gx, g_gx);
    cudaGetSymbolAddress((void**)&ya, g_ya);
    cudaGetSymbolAddress((void**)&yb, g_yb);

    const int M = BATCH * SEQ;                 // 32768
    dim3 ggrid(G3 / 64, M / 64);               // (6, 512)

    // layer 0
    gemm_nt_kernel<<<ggrid, 256>>>(x, w_ih0, b_ih, gx, M, INPUT_DIM);
    gru_rec_mma<<<BATCH, 384>>>(w_hh, b_hh, ya);

    // layers 1..4 (ping-pong ya/yb)
    float* bufs[2] = { ya, yb };
    for (int l = 1; l < NUM_LAYERS; l++) {
        const float* src = bufs[(l - 1) & 1];
        float* dst = bufs[l & 1];
        gemm_nt_kernel<<<ggrid, 256>>>(src,
                                       w_ihrest + (size_t)(l - 1) * G3 * HIDDEN,
                                       b_ih + (size_t)l * G3, gx, M, HIDDEN);
        gru_rec_mma<<<BATCH, 384>>>(w_hh + (size_t)l * G3 * HIDDEN,
                                    b_hh + (size_t)l * G3, dst);
    }

    fc_kernel<<<BATCH, OUTPUT_DIM>>>(bufs[(NUM_LAYERS - 1) & 1], fc_w, fc_b, out);
}

// round 9
// speedup vs baseline: 1.0606x; 1.0606x over previous
#include <cuda_runtime.h>
#include <cuda_fp16.h>
#include <math.h>
#include <stdint.h>

#define BATCH 64
#define SEQ 512
#define INPUT_DIM 512
#define HIDDEN 128
#define G3 384            // 3*HIDDEN
#define NUM_LAYERS 5
#define OUTPUT_DIM 96

typedef unsigned long long ull;

// ---------------- scratch (no allocs allowed) ----------------
__device__ float g_gx[BATCH * SEQ * G3];        // per-layer input gates
__device__ float g_ya[BATCH * SEQ * HIDDEN];    // ping
__device__ float g_yb[BATCH * SEQ * HIDDEN];    // pong

// ---------------- packed f32x2 helpers ----------------
__device__ __forceinline__ ull pk2(float a, float b) {
    ull r; asm("mov.b64 %0, {%1, %2};" : "=l"(r) : "f"(a), "f"(b)); return r;
}
__device__ __forceinline__ void upk2(ull v, float& a, float& b) {
    asm("mov.b64 {%0, %1}, %2;" : "=f"(a), "=f"(b) : "l"(v));
}
__device__ __forceinline__ ull ffma2(ull a, ull b, ull c) {
    ull d; asm("fma.rn.f32x2 %0, %1, %2, %3;" : "=l"(d) : "l"(a), "l"(b), "l"(c)); return d;
}
__device__ __forceinline__ float sigm_fast(float x) {
    float e = __expf(-x);
    return __fdividef(1.0f, 1.0f + e);
}
__device__ __forceinline__ float tanh_fast(float x) {
    float e = __expf(-2.0f * x);
    return 1.0f - __fdividef(2.0f * e, 1.0f + e);
}
__device__ __forceinline__ uint32_t packh2(float a, float b) {
    __half2 h = __floats2half2_rn(a, b);
    return *(uint32_t*)&h;
}

// mma.sync m16n8k16 row.col f32.f16.f16.f32 (legacy HMMA — baseline PTX, sm_80+)
__device__ __forceinline__ void mma16816(float d[4], const uint32_t a[4],
                                         uint32_t b0, uint32_t b1,
                                         const float c[4]) {
    asm volatile(
        "mma.sync.aligned.m16n8k16.row.col.f32.f16.f16.f32 "
        "{%0,%1,%2,%3}, {%4,%5,%6,%7}, {%8,%9}, {%10,%11,%12,%13};\n"
        : "=f"(d[0]), "=f"(d[1]), "=f"(d[2]), "=f"(d[3])
        : "r"(a[0]), "r"(a[1]), "r"(a[2]), "r"(a[3]),
          "r"(b0), "r"(b1),
          "f"(c[0]), "f"(c[1]), "f"(c[2]), "f"(c[3]));
}

// ---------------- GEMM: C[M x 384] = A[M x K] * W[384 x K]^T + bias ----------------
__global__ __launch_bounds__(256) void gemm_nt_kernel(
    const float* __restrict__ A, const float* __restrict__ W,
    const float* __restrict__ bias, float* __restrict__ C,
    int M, int K)
{
    __shared__ __align__(16) float Ast[16][64];
    __shared__ __align__(16) float Bst[16][64];

    const int tid = threadIdx.x;
    const int m0 = blockIdx.y * 64;
    const int n0 = blockIdx.x * 64;
    const int lrow = tid >> 2;
    const int lkc  = (tid & 3) << 2;
    const float* Ap = A + (size_t)(m0 + lrow) * K + lkc;
    const float* Wp = W + (size_t)(n0 + lrow) * K + lkc;
    const int tx = tid & 15;
    const int ty = tid >> 4;

    ull acc[4][2];
#pragma unroll
    for (int i = 0; i < 4; i++) { acc[i][0] = pk2(0.f, 0.f); acc[i][1] = pk2(0.f, 0.f); }

    float4 av = *(const float4*)(Ap);
    float4 bv = *(const float4*)(Wp);

    for (int kt = 0; kt < K; kt += 16) {
        __syncthreads();
        Ast[lkc + 0][lrow] = av.x; Ast[lkc + 1][lrow] = av.y;
        Ast[lkc + 2][lrow] = av.z; Ast[lkc + 3][lrow] = av.w;
        Bst[lkc + 0][lrow] = bv.x; Bst[lkc + 1][lrow] = bv.y;
        Bst[lkc + 2][lrow] = bv.z; Bst[lkc + 3][lrow] = bv.w;
        __syncthreads();
        if (kt + 16 < K) {
            av = *(const float4*)(Ap + kt + 16);
            bv = *(const float4*)(Wp + kt + 16);
        }
#pragma unroll
        for (int k = 0; k < 16; k++) {
            float4 a4 = *(const float4*)&Ast[k][ty << 2];
            ulonglong2 b2 = *(const ulonglong2*)&Bst[k][tx << 2];
            ull pa;
            pa = pk2(a4.x, a4.x);
            acc[0][0] = ffma2(pa, b2.x, acc[0][0]); acc[0][1] = ffma2(pa, b2.y, acc[0][1]);
            pa = pk2(a4.y, a4.y);
            acc[1][0] = ffma2(pa, b2.x, acc[1][0]); acc[1][1] = ffma2(pa, b2.y, acc[1][1]);
            pa = pk2(a4.z, a4.z);
            acc[2][0] = ffma2(pa, b2.x, acc[2][0]); acc[2][1] = ffma2(pa, b2.y, acc[2][1]);
            pa = pk2(a4.w, a4.w);
            acc[3][0] = ffma2(pa, b2.x, acc[3][0]); acc[3][1] = ffma2(pa, b2.y, acc[3][1]);
        }
    }
#pragma unroll
    for (int i = 0; i < 4; i++) {
        int m = m0 + (ty << 2) + i;
        float c0, c1, c2, c3;
        upk2(acc[i][0], c0, c1);
        upk2(acc[i][1], c2, c3);
        int n = n0 + (tx << 2);
        float* Cp = C + (size_t)m * G3 + n;
        Cp[0] = c0 + bias[n + 0];
        Cp[1] = c1 + bias[n + 1];
        Cp[2] = c2 + bias[n + 2];
        Cp[3] = c3 + bias[n + 3];
    }
}

// ---------------- GRU recurrence via mma.sync, single-barrier steps ----------------
// One CTA per batch, 256 threads = 8 warps. Warp w owns hidden units
// [16w, 16w+16): its three m16 tiles are the r/z/n gate rows for those units
// (rows u, u+128, u+256). With the m16n8k16 D layout, lane 4g then holds
// gh_r/gh_z/gh_n for units 16w+g and 16w+8+g in-lane -> gates computed with
// no gh smem round-trip and ONE barrier per step. B cols: col0 = fp16_hi(h),
// col1 = fp16_lo(h); gh = D[:,0] + D[:,1] recovers ~fp32 h transport.
__global__ __launch_bounds__(256, 1) void gru_rec_mma(
    const float* __restrict__ w_hh,   // [384][128]
    const float* __restrict__ b_hh,   // [384]
    float* __restrict__ y)            // [BATCH][SEQ][HIDDEN]
{
    // h double buffer: [buf][hi/lo][128] halfs
    __shared__ __align__(16) __half hbuf[2][2][HIDDEN];

    const int b = blockIdx.x;
    const int tid = threadIdx.x;
    const int wid = tid >> 5;       // 0..7
    const int lane = tid & 31;
    const int g  = lane >> 2;       // 0..7
    const int tg = lane & 3;        // 0..3
    const bool act = (tg == 0);
    const int u0 = wid * 16 + g;    // first hidden unit this lane handles
    const int u1 = u0 + 8;          // second

    // ---- preload W_hh rows into A fragments (fp32 -> fp16) ----
    // tile i = gate i, rows mbase = i*128 + wid*16
    uint32_t afr[3][8][4];
#pragma unroll
    for (int i = 0; i < 3; i++) {
        const int mbase = i * HIDDEN + wid * 16;
        const float* r0p = w_hh + (size_t)(mbase + g) * HIDDEN;
        const float* r1p = w_hh + (size_t)(mbase + 8 + g) * HIDDEN;
#pragma unroll
        for (int kt = 0; kt < 8; kt++) {
            const int c0 = kt * 16 + 2 * tg;
            float2 v00 = *(const float2*)(r0p + c0);
            float2 v10 = *(const float2*)(r1p + c0);
            float2 v01 = *(const float2*)(r0p + c0 + 8);
            float2 v11 = *(const float2*)(r1p + c0 + 8);
            afr[i][kt][0] = packh2(v00.x, v00.y);
            afr[i][kt][1] = packh2(v10.x, v10.y);
            afr[i][kt][2] = packh2(v01.x, v01.y);
            afr[i][kt][3] = packh2(v11.x, v11.y);
        }
    }

    // biases for this lane's two units (active lanes only)
    float br0 = 0.f, bz0 = 0.f, bn0 = 0.f, br1 = 0.f, bz1 = 0.f, bn1 = 0.f;
    if (act) {
        br0 = b_hh[u0];            br1 = b_hh[u1];
        bz0 = b_hh[u0 + HIDDEN];   bz1 = b_hh[u1 + HIDDEN];
        bn0 = b_hh[u0 + 2*HIDDEN]; bn1 = b_hh[u1 + 2*HIDDEN];
    }

    // zero both h buffers (2*2*128 halfs = 256 uint32)
    ((uint32_t*)hbuf)[tid] = 0u;

    const float* gxb = g_gx + (size_t)b * SEQ * G3;
    float* yb = y + (size_t)b * SEQ * HIDDEN;

    // prefetch t=0 gx for both units
    float xr0 = 0.f, xz0 = 0.f, xn0 = 0.f, xr1 = 0.f, xz1 = 0.f, xn1 = 0.f;
    if (act) {
        xr0 = gxb[u0];            xr1 = gxb[u1];
        xz0 = gxb[u0 + HIDDEN];   xz1 = gxb[u1 + HIDDEN];
        xn0 = gxb[u0 + 2*HIDDEN]; xn1 = gxb[u1 + 2*HIDDEN];
    }
    float h0 = 0.f, h1 = 0.f;   // register-resident h for our two units
    __syncthreads();

    for (int t = 0; t < SEQ; t++) {
        // prefetch next step's gx early (covers DRAM/L2 latency)
        float nxr0 = 0.f, nxz0 = 0.f, nxn0 = 0.f;
        float nxr1 = 0.f, nxz1 = 0.f, nxn1 = 0.f;
        if (act && t + 1 < SEQ) {
            const float* g1 = gxb + (t + 1) * G3;
            nxr0 = __ldg(g1 + u0);            nxr1 = __ldg(g1 + u1);
            nxz0 = __ldg(g1 + u0 + HIDDEN);   nxz1 = __ldg(g1 + u1 + HIDDEN);
            nxn0 = __ldg(g1 + u0 + 2*HIDDEN); nxn1 = __ldg(g1 + u1 + 2*HIDDEN);
        }

        // ---- build B fragments from hbuf[t&1] (identical in every warp) ----
        uint32_t b0[8], b1[8];
#pragma unroll
        for (int kt = 0; kt < 8; kt++) { b0[kt] = 0u; b1[kt] = 0u; }
        if (lane < 8) {
            // col g==0 <- hi halfs, col g==1 <- lo halfs
            const uint32_t* src = (const uint32_t*)hbuf[t & 1][lane >> 2];
#pragma unroll
            for (int kt = 0; kt < 8; kt++) {
                b0[kt] = src[kt * 8 + tg];
                b1[kt] = src[kt * 8 + 4 + tg];
            }
        }

        // ---- 3 gate tiles, 2 interleaved accumulator chains each ----
        float gh[3][2];
#pragma unroll
        for (int i = 0; i < 3; i++) {
            float da[4] = {0.f, 0.f, 0.f, 0.f};
            float db[4] = {0.f, 0.f, 0.f, 0.f};
#pragma unroll
            for (int kt = 0; kt < 8; kt += 2) {
                mma16816(da, afr[i][kt],     b0[kt],     b1[kt],     da);
                mma16816(db, afr[i][kt + 1], b0[kt + 1], b1[kt + 1], db);
            }
            gh[i][0] = (da[0] + db[0]) + (da[1] + db[1]);   // unit u0: col0+col1
            gh[i][1] = (da[2] + db[2]) + (da[3] + db[3]);   // unit u1
        }

        // ---- gates in-lane, write h hi/lo to the other buffer ----
        if (act) {
            float r0g = sigm_fast(xr0 + gh[0][0] + br0);
            float r1g = sigm_fast(xr1 + gh[0][1] + br1);
            float z0g = sigm_fast(xz0 + gh[1][0] + bz0);
            float z1g = sigm_fast(xz1 + gh[1][1] + bz1);
            float n0g = tanh_fast(xn0 + r0g * (gh[2][0] + bn0));
            float n1g = tanh_fast(xn1 + r1g * (gh[2][1] + bn1));
            float hn0 = (1.0f - z0g) * n0g + z0g * h0;
            float hn1 = (1.0f - z1g) * n1g + z1g * h1;
            h0 = hn0; h1 = hn1;

            __half hi0 = __float2half_rn(hn0);
            __half hi1 = __float2half_rn(hn1);
            __half lo0 = __float2half_rn(hn0 - __half2float(hi0));
            __half lo1 = __float2half_rn(hn1 - __half2float(hi1));
            const int nb = (t + 1) & 1;
            hbuf[nb][0][u0] = hi0;
            hbuf[nb][0][u1] = hi1;
            hbuf[nb][1][u0] = lo0;
            hbuf[nb][1][u1] = lo1;

            float* yt = yb + t * HIDDEN;
            yt[u0] = hn0;
            yt[u1] = hn1;
        }
        __syncthreads();

        xr0 = nxr0; xz0 = nxz0; xn0 = nxn0;
        xr1 = nxr1; xz1 = nxz1; xn1 = nxn1;
    }
}

// ---------------- final FC on last timestep ----------------
__global__ void fc_kernel(const float* __restrict__ yfinal,
                          const float* __restrict__ fc_w,
                          const float* __restrict__ fc_b,
                          float* __restrict__ out)
{
    const int b = blockIdx.x;
    const int o = threadIdx.x;   // 0..95
    const float* h = yfinal + ((size_t)b * SEQ + (SEQ - 1)) * HIDDEN;
    const float* w = fc_w + (size_t)o * HIDDEN;
    float acc = fc_b[o];
#pragma unroll 16
    for (int k = 0; k < HIDDEN; k++) acc = fmaf(h[k], w[k], acc);
    out[b * OUTPUT_DIM + o] = acc;
}

// ---------------- host launch ----------------
extern "C" void kernel_launch(void* const* d_in, const int* in_sizes, int n_in,
                              void* d_out, int out_size)
{
    const float* x        = (const float*)d_in[0];  // [64,512,512]
    const float* w_ih0    = (const float*)d_in[1];  // [384,512]
    const float* w_ihrest = (const float*)d_in[2];  // [4,384,128]
    const float* w_hh     = (const float*)d_in[3];  // [5,384,128]
    const float* b_ih     = (const float*)d_in[4];  // [5,384]
    const float* b_hh     = (const float*)d_in[5];  // [5,384]
    const float* fc_w     = (const float*)d_in[6];  // [96,128]
    const float* fc_b     = (const float*)d_in[7];  // [96]
    float* out = (float*)d_out;

    float *gx, *ya, *yb;
    cudaGetSymbolAddress((void**)&gx, g_gx);
    cudaGetSymbolAddress((void**)&ya, g_ya);
    cudaGetSymbolAddress((void**)&yb, g_yb);

    const int M = BATCH * SEQ;                 // 32768
    dim3 ggrid(G3 / 64, M / 64);               // (6, 512)

    // layer 0
    gemm_nt_kernel<<<ggrid, 256>>>(x, w_ih0, b_ih, gx, M, INPUT_DIM);
    gru_rec_mma<<<BATCH, 256>>>(w_hh, b_hh, ya);

    // layers 1..4 (ping-pong ya/yb)
    float* bufs[2] = { ya, yb };
    for (int l = 1; l < NUM_LAYERS; l++) {
        const float* src = bufs[(l - 1) & 1];
        float* dst = bufs[l & 1];
        gemm_nt_kernel<<<ggrid, 256>>>(src,
                                       w_ihrest + (size_t)(l - 1) * G3 * HIDDEN,
                                       b_ih + (size_t)l * G3, gx, M, HIDDEN);
        gru_rec_mma<<<BATCH, 256>>>(w_hh + (size_t)l * G3 * HIDDEN,
                                    b_hh + (size_t)l * G3, dst);
    }

    fc_kernel<<<BATCH, OUTPUT_DIM>>>(bufs[(NUM_LAYERS - 1) & 1], fc_w, fc_b, out);
}